// round 3
// baseline (speedup 1.0000x reference)
#include <cuda_runtime.h>
#include <math.h>

#define NN 8192
#define BB 4
#define SS 12
#define LL 5
#define KK 16
#define EE 131072

// ---------------- static device scratch (no allocations allowed) ----------------
// Zero-initialized at module load; every kernel that dirties g_cell/g_bits/g_deg
// restores the all-zero invariant before the round ends, so CUDA graph replays
// always see a consistent state.
__device__ float        g_cell[(size_t)NN * NN];          // 256 MB sparse accumulation scratch
__device__ unsigned int g_bits[(size_t)NN * NN / 32];     // 8 MB occupancy bitmask
__device__ float        g_xp[BB * NN * SS];
__device__ float        g_c1[BB * NN * SS];
__device__ float        g_c2[BB * NN * SS];
__device__ float        g_c4[BB * NN * SS];
__device__ float        g_c5[BB * NN * SS];
__device__ float        g_ha[NN], g_hb[NN];
__device__ float        g_colsum[NN];
__device__ float        g_extra[BB * SS];
__device__ float        g_w[EE];                          // normalized per-edge weight (0 for dup non-reps)
__device__ unsigned char g_rep[EE];

// CSR (by destination row i = edges[0][k]) for each edge set
__device__ int g_deg[2][NN];                              // self-zeroing (cleared inside k_scan)
__device__ int g_cursor[2][NN];
__device__ int g_rowptr[2][NN + 1];
__device__ int g_csr1[EE], g_csr2[EE];

__device__ __forceinline__ float* feat_ptr(int code) {
    switch (code) {
        case 0: return g_xp;
        case 1: return g_c1;
        case 2: return g_c2;
        case 3: return g_c4;
        default: return g_c5;
    }
}
__device__ __forceinline__ int* csr_ptr(int set) { return set == 0 ? g_csr1 : g_csr2; }

// fast activations (inputs are O(1); __expf error ~1e-7 rel, fine vs 1e-3 gate)
__device__ __forceinline__ float sigf(float x) { return 1.0f / (1.0f + __expf(-x)); }
__device__ __forceinline__ float tanhfast(float x) { return 2.0f / (1.0f + __expf(-2.0f * x)) - 1.0f; }

// ---------------- fused setup: transpose + degree histograms ----------------

// x: (B, S, N) -> g_xp[(b*N+n)*S + s]; plus degree histograms for both edge sets
__global__ void k_setup(const float* __restrict__ x,
                        const int* __restrict__ e1, const int* __restrict__ e2) {
    int idx = blockIdx.x * blockDim.x + threadIdx.x;
    if (idx < BB * SS * NN) {
        int n = idx % NN;
        int bs = idx / NN;
        int s = bs % SS;
        int b = bs / SS;
        g_xp[((size_t)(b * NN + n)) * SS + s] = x[idx];
    }
    if (idx < EE) {
        atomicAdd(&g_deg[0][e1[idx]], 1);
    } else if (idx < 2 * EE) {
        atomicAdd(&g_deg[1][e2[idx - EE]], 1);
    }
}

// one block, 1024 threads, 8 rows each: exclusive scans of both g_deg arrays ->
// rowptr/cursor. Re-zeros g_deg (restores invariant for the next replay).
__global__ void k_scan() {
    __shared__ int sh[1024];
    int t = threadIdx.x;
    for (int set = 0; set < 2; set++) {
        int loc[8];
        int s = 0;
#pragma unroll
        for (int u = 0; u < 8; u++) {
            loc[u] = s;
            s += g_deg[set][t * 8 + u];
            g_deg[set][t * 8 + u] = 0;
        }
        sh[t] = s;
        __syncthreads();
        for (int off = 1; off < 1024; off <<= 1) {
            int v = (t >= off) ? sh[t - off] : 0;
            __syncthreads();
            sh[t] += v;
            __syncthreads();
        }
        int base = (t > 0) ? sh[t - 1] : 0;
#pragma unroll
        for (int u = 0; u < 8; u++) {
            int p = base + loc[u];
            g_rowptr[set][t * 8 + u] = p;
            g_cursor[set][t * 8 + u] = p;
        }
        if (t == 1023) g_rowptr[set][NN] = sh[1023];
        __syncthreads();
    }
}

__global__ void k_scatter(const int* __restrict__ e1, const int* __restrict__ e2) {
    int idx = blockIdx.x * blockDim.x + threadIdx.x;
    if (idx < EE) {
        int pos = atomicAdd(&g_cursor[0][e1[idx]], 1);
        g_csr1[pos] = idx;
    } else if (idx < 2 * EE) {
        int k = idx - EE;
        int pos = atomicAdd(&g_cursor[1][e2[k]], 1);
        g_csr2[pos] = k;
    }
}

// ---------------- GAT round kernels ----------------

// per-node GAT logit halves from BATCH-0 features (reference indexes rows 0..N-1
// of the (B*N, S) matrix), plus zeroing of colsum/extra for this round.
__global__ void k_prep(int xcode, const float* __restrict__ W, const float* __restrict__ av) {
    __shared__ float sW[SS * SS], sa[2 * SS];
    int t = threadIdx.x;
    if (t < SS * SS) sW[t] = W[t];
    if (t < 2 * SS)  sa[t] = av[t];
    __syncthreads();
    int n = blockIdx.x * blockDim.x + t;
    if (n >= NN) return;
    const float* Xin = feat_ptr(xcode);       // batch 0 = first N*S floats
    float xr[SS];
#pragma unroll
    for (int s = 0; s < SS; s++) xr[s] = Xin[n * SS + s];
    float ha = 0.f, hb = 0.f;
#pragma unroll
    for (int sp = 0; sp < SS; sp++) {
        float h = 0.f;
#pragma unroll
        for (int s = 0; s < SS; s++) h += xr[s] * sW[s * SS + sp];
        ha += h * sa[sp];
        hb += h * sa[SS + sp];
    }
    g_ha[n] = ha;
    g_hb[n] = hb;
    g_colsum[n] = 0.f;
    if (n < BB * SS) g_extra[n] = 0.f;
}

// pass 1: accumulate val per cell (duplicate edges accumulate BEFORE exp, matching
// the reference's .at[].add), elect one representative edge per occupied cell.
__global__ void k_edge1(const int* __restrict__ edges,
                        const float* __restrict__ lwp, const float* __restrict__ lbp) {
    int k = blockIdx.x * blockDim.x + threadIdx.x;
    if (k >= EE) return;
    int i = edges[k];
    int j = edges[EE + k];
    float e = g_ha[i] + g_hb[j];
    e = (e > 0.f) ? e : 0.2f * e;                 // leaky_relu(0.2)
    float val = e * lwp[0] + lbp[0];
    unsigned int c = (unsigned int)i * NN + (unsigned int)j;
    atomicAdd(&g_cell[c], val);
    unsigned int old = atomicOr(&g_bits[c >> 5], 1u << (c & 31u));
    g_rep[k] = (((old >> (c & 31u)) & 1u) == 0u) ? 1 : 0;
}

// pass 2: representatives exponentiate and build column sums (softmax axis=0).
// Non-edge cells contribute exp(NEG)=0; nothing to add for them.
__global__ void k_edge2(const int* __restrict__ edges) {
    int k = blockIdx.x * blockDim.x + threadIdx.x;
    if (k >= EE) return;
    if (!g_rep[k]) return;
    int i = edges[k];
    int j = edges[EE + k];
    unsigned int c = (unsigned int)i * NN + (unsigned int)j;
    float p = __expf(g_cell[c]);
    g_cell[c] = p;
    atomicAdd(&g_colsum[j], p);
}

// pass 3: normalized weight per edge -> g_w; restore g_cell/g_bits zero invariant;
// empty-column (uniform 1/N softmax) correction accumulated into g_extra.
__global__ void k_wfix(const int* __restrict__ edges, int xcode) {
    int t = blockIdx.x * blockDim.x + threadIdx.x;
    if (t < EE) {
        if (g_rep[t]) {
            int i = edges[t];
            int j = edges[EE + t];
            unsigned int c = (unsigned int)i * NN + (unsigned int)j;
            g_w[t] = g_cell[c] / g_colsum[j];
            g_cell[c] = 0.f;
            g_bits[c >> 5] = 0u;          // all writers store 0 -> race-free
        } else {
            g_w[t] = 0.f;
        }
    }
    if (t < NN) {
        if (g_colsum[t] == 0.f) {         // column with no edges -> uniform softmax
            const float* X = feat_ptr(xcode);
            for (int b = 0; b < BB; b++)
#pragma unroll
            for (int s = 0; s < SS; s++)
                atomicAdd(&g_extra[b * SS + s], X[((size_t)b * NN + t) * SS + s]);
        }
    }
}

// pass 4 (fused SpMM gather + GCN): thread = (i, b). Atomic-free.
// z[b,i,:] = sum_{edges k with dest i} w_k * X[b, src_k, :]  (+ extra/N)
// C[b,i,:] = leaky_relu(z @ gcnW^T + gcnb, 0.01)
__global__ void k_gathergcn(const int* __restrict__ edges, int set,
                            int xcode, int outcode,
                            const float* __restrict__ gcnW, const float* __restrict__ gcnb) {
    __shared__ float sW[SS * SS], sb[SS], sx[BB * SS];
    int t = threadIdx.x;
    if (t < SS * SS) sW[t] = gcnW[t];
    if (t < SS)      sb[t] = gcnb[t];
    if (t < BB * SS) sx[t] = g_extra[t] * (1.0f / NN);
    __syncthreads();
    int r = blockIdx.x * blockDim.x + t;
    if (r >= BB * NN) return;
    int i = r >> 2;                 // 4 adjacent lanes share row i (broadcast csr/w loads)
    int b = r & 3;
    const int* csr = csr_ptr(set);
    const float* X = feat_ptr(xcode) + (size_t)b * NN * SS;
    float acc[SS];
#pragma unroll
    for (int s = 0; s < SS; s++) acc[s] = sx[b * SS + s];
    int beg = g_rowptr[set][i], end = g_rowptr[set][i + 1];
    for (int p = beg; p < end; p++) {
        int k = csr[p];
        float w = g_w[k];
        if (w != 0.f) {
            const float* xr = X + (size_t)edges[EE + k] * SS;
#pragma unroll
            for (int s = 0; s < SS; s++) acc[s] += w * xr[s];
        }
    }
    float* C = feat_ptr(outcode) + ((size_t)b * NN + i) * SS;
#pragma unroll
    for (int sp = 0; sp < SS; sp++) {
        float v = sb[sp];
#pragma unroll
        for (int s = 0; s < SS; s++) v += acc[s] * sW[sp * SS + s];
        C[sp] = (v > 0.f) ? v : 0.01f * v;
    }
}

// ---------------- LSTM (2 layers, lockstep) + attention/FC tail ----------------

__device__ __forceinline__ void lstm_cell(const float* xt, float* h, float* c,
                                          const float* Wih, const float* Whh,
                                          const float* bias) {
    float zz[20];
#pragma unroll
    for (int u = 0; u < 20; u++) {
        float z = bias[u];
#pragma unroll
        for (int l = 0; l < 5; l++) z += xt[l] * Wih[u * 5 + l] + h[l] * Whh[u * 5 + l];
        zz[u] = z;
    }
#pragma unroll
    for (int u = 0; u < 5; u++) {
        float ig = sigf(zz[u]);
        float fg = sigf(zz[5 + u]);
        float gg = tanhfast(zz[10 + u]);
        float og = sigf(zz[15 + u]);
        c[u] = fg * c[u] + ig * gg;
        h[u] = og * tanhfast(c[u]);
    }
}

__global__ void __launch_bounds__(256)
k_lstm(const float* __restrict__ Wih0, const float* __restrict__ Whh0,
       const float* __restrict__ bih0, const float* __restrict__ bhh0,
       const float* __restrict__ Wih1, const float* __restrict__ Whh1,
       const float* __restrict__ bih1, const float* __restrict__ bhh1,
       const float* __restrict__ fc1W, const float* __restrict__ fc1b,
       const float* __restrict__ fc2W, const float* __restrict__ fc2b,
       const float* __restrict__ fc3W, const float* __restrict__ fc3b,
       float* __restrict__ out, int write_a) {
    __shared__ float sWih0[100], sWhh0[100], sb0[20];
    __shared__ float sWih1[100], sWhh1[100], sb1[20];
    __shared__ float sfc1W[KK * (SS - 1)], sfc1b[KK];
    __shared__ float sfc2W[LL * KK], sfc2b[LL];
    __shared__ float sfc3W[KK + LL], sfc3b0;
    int t = threadIdx.x;
    if (t < 100) { sWih0[t] = Wih0[t]; sWhh0[t] = Whh0[t]; sWih1[t] = Wih1[t]; sWhh1[t] = Whh1[t]; }
    if (t < 20)  { sb0[t] = bih0[t] + bhh0[t]; sb1[t] = bih1[t] + bhh1[t]; }
    if (t < KK * (SS - 1)) sfc1W[t] = fc1W[t];
    if (t < KK)  sfc1b[t] = fc1b[t];
    if (t < LL * KK) sfc2W[t] = fc2W[t];
    if (t < LL)  sfc2b[t] = fc2b[t];
    if (t < KK + LL) sfc3W[t] = fc3W[t];
    if (t == 0)  sfc3b0 = fc3b[0];
    __syncthreads();

    int r = blockIdx.x * blockDim.x + t;   // row in [0, B*N)
    if (r >= BB * NN) return;
    size_t base = (size_t)r * SS;          // *4 bytes = 48B -> 16B aligned

    // coalesced vectorized feature loads: 3 float4 per feature array
    float f[5][SS];
    {
        const float* srcs[5] = { g_xp + base, g_c1 + base, g_c2 + base, g_c4 + base, g_c5 + base };
#pragma unroll
        for (int l = 0; l < 5; l++) {
            const float4* p4 = reinterpret_cast<const float4*>(srcs[l]);
#pragma unroll
            for (int q = 0; q < 3; q++) {
                float4 v = p4[q];
                f[l][q * 4 + 0] = v.x; f[l][q * 4 + 1] = v.y;
                f[l][q * 4 + 2] = v.z; f[l][q * 4 + 3] = v.w;
            }
        }
    }

    float h0[5] = {0, 0, 0, 0, 0}, c0[5] = {0, 0, 0, 0, 0};
    float h1[5] = {0, 0, 0, 0, 0}, c1v[5] = {0, 0, 0, 0, 0};
    float Hc[5][KK];
#pragma unroll
    for (int l = 0; l < 5; l++)
#pragma unroll
        for (int k = 0; k < KK; k++) Hc[l][k] = sfc1b[k];

#pragma unroll
    for (int tt = 0; tt < SS; tt++) {
        float xt[5];
#pragma unroll
        for (int l = 0; l < 5; l++) xt[l] = f[l][tt];
        lstm_cell(xt, h0, c0, sWih0, sWhh0, sb0);
        lstm_cell(h0, h1, c1v, sWih1, sWhh1, sb1);
        if (tt < SS - 1) {
#pragma unroll
            for (int l = 0; l < 5; l++)
#pragma unroll
                for (int k = 0; k < KK; k++)
                    Hc[l][k] += h1[l] * sfc1W[k * (SS - 1) + tt];
        }
    }
    // h1 is now ht = lstm_out[:, -1, :]
    float a[5];
#pragma unroll
    for (int l = 0; l < 5; l++) {
        float acc = 0.f;
#pragma unroll
        for (int m = 0; m < 5; m++) {
            float hn = sfc2b[m];
#pragma unroll
            for (int k = 0; k < KK; k++) hn += Hc[l][k] * sfc2W[m * KK + k];
            acc += hn * h1[m];
        }
        a[l] = sigf(acc);
    }
    float y = sfc3b0;
#pragma unroll
    for (int k = 0; k < KK; k++) {
        float vt = 0.f;
#pragma unroll
        for (int l = 0; l < 5; l++) vt += a[l] * Hc[l][k];
        y += vt * sfc3W[k];
    }
#pragma unroll
    for (int l = 0; l < 5; l++) y += h1[l] * sfc3W[KK + l];

    out[r] = y;
    if (write_a) {
#pragma unroll
        for (int l = 0; l < 5; l++) out[BB * NN + (size_t)r * 5 + l] = a[l];
    }
}

// ---------------- host orchestration (launches only; graph-capture safe) --------

static void gat_round(int xin, const int* edges, int set,
                      const float* W, const float* av,
                      const float* lw, const float* lb,
                      const float* gcnW, const float* gcnb, int outc) {
    k_prep<<<NN / 256, 256>>>(xin, W, av);
    k_edge1<<<EE / 256, 256>>>(edges, lw, lb);
    k_edge2<<<EE / 256, 256>>>(edges);
    k_wfix<<<EE / 256, 256>>>(edges, xin);
    k_gathergcn<<<(BB * NN + 255) / 256, 256>>>(edges, set, xin, outc, gcnW, gcnb);
}

extern "C" void kernel_launch(void* const* d_in, const int* in_sizes, int n_in,
                              void* d_out, int out_size) {
    const float* x    = (const float*)d_in[0];
    const int*   e1   = (const int*)  d_in[1];
    const int*   e2   = (const int*)  d_in[2];
    const float* g1W  = (const float*)d_in[3];
    const float* g1a  = (const float*)d_in[4];
    const float* g1lw = (const float*)d_in[5];
    const float* g1lb = (const float*)d_in[6];
    const float* g2W  = (const float*)d_in[7];
    const float* g2a  = (const float*)d_in[8];
    const float* g2lw = (const float*)d_in[9];
    const float* g2lb = (const float*)d_in[10];
    const float* gcnW = (const float*)d_in[11];
    const float* gcnb = (const float*)d_in[12];
    const float* Wih0 = (const float*)d_in[13];
    const float* Whh0 = (const float*)d_in[14];
    const float* bih0 = (const float*)d_in[15];
    const float* bhh0 = (const float*)d_in[16];
    const float* Wih1 = (const float*)d_in[17];
    const float* Whh1 = (const float*)d_in[18];
    const float* bih1 = (const float*)d_in[19];
    const float* bhh1 = (const float*)d_in[20];
    const float* fc1W = (const float*)d_in[21];
    const float* fc1b = (const float*)d_in[22];
    const float* fc2W = (const float*)d_in[23];
    const float* fc2b = (const float*)d_in[24];
    const float* fc3W = (const float*)d_in[25];
    const float* fc3b = (const float*)d_in[26];
    float* out = (float*)d_out;

    // setup: transpose + degree hist (both sets) -> scan (both) -> scatter (both)
    k_setup<<<(BB * SS * NN + 255) / 256, 256>>>(x, e1, e2);
    k_scan<<<1, 1024>>>();
    k_scatter<<<(2 * EE + 255) / 256, 256>>>(e1, e2);

    gat_round(0, e1, 0, g1W, g1a, g1lw, g1lb, gcnW, gcnb, 1);  // xp  -> c1
    gat_round(1, e1, 0, g1W, g1a, g1lw, g1lb, gcnW, gcnb, 2);  // c1  -> c2
    gat_round(0, e2, 1, g2W, g2a, g2lw, g2lb, gcnW, gcnb, 3);  // xp  -> c4
    gat_round(3, e2, 1, g2W, g2a, g2lw, g2lb, gcnW, gcnb, 4);  // c4  -> c5

    int write_a = (out_size >= BB * NN * (1 + LL)) ? 1 : 0;
    k_lstm<<<(BB * NN + 255) / 256, 256>>>(Wih0, Whh0, bih0, bhh0,
                                           Wih1, Whh1, bih1, bhh1,
                                           fc1W, fc1b, fc2W, fc2b, fc3W, fc3b,
                                           out, write_a);
}

// round 8
// speedup vs baseline: 1.2233x; 1.2233x over previous
#include <cuda_runtime.h>
#include <math.h>

#define NN 8192
#define BB 4
#define SS 12
#define LL 5
#define KK 16
#define EE 131072

// ---------------- static device scratch (no allocations allowed) ----------------
// Zero-initialized at module load. g_deg restores its zero invariant inside
// k_scan every call; everything else is fully overwritten each call, so CUDA
// graph replays are deterministic.
__device__ float        g_xp[BB * NN * SS];
__device__ float        g_c1[BB * NN * SS];
__device__ float        g_c2[BB * NN * SS];
__device__ float        g_c4[BB * NN * SS];
__device__ float        g_c5[BB * NN * SS];
__device__ float        g_ha[2][NN], g_hb[2][NN];
__device__ float        g_colsum[2][NN];
__device__ float        g_extra[2][BB * SS];

// CSR-ordered per-position data (position p = slot in dest-row-sorted order)
__device__ int           g_deg[2][NN];       // self-zeroing (cleared inside k_scan)
__device__ int           g_cursor[2][NN];
__device__ int           g_rowptr[2][NN + 1];
__device__ int           g_csri[2][EE];      // dest node i at position p
__device__ int           g_csrj[2][EE];      // src  node j at position p
__device__ int           g_multp[2][EE];     // multiplicity if representative, else 0
__device__ float         g_wp[2][EE];        // exp value at position p (0 for non-reps)
__device__ unsigned char g_colhas[2][NN];    // column j has >=1 edge (stable across replays)

__device__ __forceinline__ float* feat_ptr(int code) {
    switch (code) {
        case 0: return g_xp;
        case 1: return g_c1;
        case 2: return g_c2;
        case 3: return g_c4;
        default: return g_c5;
    }
}

// fast activations (__expf rel err ~1e-7; correctness gate is 1e-3)
__device__ __forceinline__ float sigf(float x) { return 1.0f / (1.0f + __expf(-x)); }
__device__ __forceinline__ float tanhfast(float x) { return 2.0f / (1.0f + __expf(-2.0f * x)) - 1.0f; }

// ---------------- setup: transpose + degree hist + column masks ----------------

__global__ void k_setup(const float* __restrict__ x,
                        const int* __restrict__ e1, const int* __restrict__ e2) {
    int idx = blockIdx.x * blockDim.x + threadIdx.x;
    if (idx < BB * SS * NN) {
        int n = idx % NN;
        int bs = idx / NN;
        int s = bs % SS;
        int b = bs / SS;
        g_xp[((size_t)(b * NN + n)) * SS + s] = x[idx];
    }
    if (idx < EE) {
        atomicAdd(&g_deg[0][e1[idx]], 1);
        g_colhas[0][e1[EE + idx]] = 1;       // deterministic overwrite each replay
    } else if (idx < 2 * EE) {
        int k = idx - EE;
        atomicAdd(&g_deg[1][e2[k]], 1);
        g_colhas[1][e2[EE + k]] = 1;
    }
}

// one block: exclusive scans of both g_deg arrays -> rowptr/cursor; re-zero g_deg.
__global__ void k_scan() {
    __shared__ int sh[1024];
    int t = threadIdx.x;
    for (int set = 0; set < 2; set++) {
        int loc[8];
        int s = 0;
#pragma unroll
        for (int u = 0; u < 8; u++) {
            loc[u] = s;
            s += g_deg[set][t * 8 + u];
            g_deg[set][t * 8 + u] = 0;
        }
        sh[t] = s;
        __syncthreads();
        for (int off = 1; off < 1024; off <<= 1) {
            int v = (t >= off) ? sh[t - off] : 0;
            __syncthreads();
            sh[t] += v;
            __syncthreads();
        }
        int base = (t > 0) ? sh[t - 1] : 0;
#pragma unroll
        for (int u = 0; u < 8; u++) {
            int p = base + loc[u];
            g_rowptr[set][t * 8 + u] = p;
            g_cursor[set][t * 8 + u] = p;
        }
        if (t == 1023) g_rowptr[set][NN] = sh[1023];
        __syncthreads();
    }
}

// scatter edges into CSR-position order, materializing (i, j) per position so the
// round kernels never chase edge indices again.
__global__ void k_scatter(const int* __restrict__ e1, const int* __restrict__ e2) {
    int idx = blockIdx.x * blockDim.x + threadIdx.x;
    if (idx < EE) {
        int i = e1[idx], j = e1[EE + idx];
        int pos = atomicAdd(&g_cursor[0][i], 1);
        g_csri[0][pos] = i;
        g_csrj[0][pos] = j;
    } else if (idx < 2 * EE) {
        int k = idx - EE;
        int i = e2[k], j = e2[EE + k];
        int pos = atomicAdd(&g_cursor[1][i], 1);
        g_csri[1][pos] = i;
        g_csrj[1][pos] = j;
    }
}

// per (set,row): O(d^2) duplicate detection over the contiguous csrj slice ->
// multiplicity per representative position. Duplicate (i,j) edges carry
// IDENTICAL pre-softmax vals, so the accumulated cell value = mult * val,
// independent of which round we're in. (Scatter order is nondeterministic, but
// multiplicity/rep assignment is recomputed consistently within every replay and
// all downstream reductions are permutation-invariant.)
__global__ void k_dedup() {
    int tid = blockIdx.x * blockDim.x + threadIdx.x;
    if (tid >= 2 * NN) return;
    int set = tid >> 13;
    int i = tid & (NN - 1);
    const int* csrj = g_csrj[set];
    int beg = g_rowptr[set][i], end = g_rowptr[set][i + 1];
    for (int p = beg; p < end; p++) {
        int jp = csrj[p];
        int m = 0;
        bool rep = true;
        for (int q = beg; q < end; q++) {
            if (csrj[q] == jp) {
                if (q < p) { rep = false; break; }
                m++;
            }
        }
        g_multp[set][p] = rep ? m : 0;
    }
}

// ---------------- fused GAT super-round kernels (both edge sets at once) --------

// per-node logit halves for BOTH sets; set0 uses (xcodeA, WA, avA), set1 (xcodeB,...).
// Reference indexes only rows 0..N-1 of the (B*N,S) matrix => batch-0 features.
// Also zeroes colsum/extra for the round.
__global__ void k_prep2(int xcodeA, const float* __restrict__ WA, const float* __restrict__ avA,
                        int xcodeB, const float* __restrict__ WB, const float* __restrict__ avB) {
    __shared__ float sW[2][SS * SS], sa[2][2 * SS];
    int t = threadIdx.x;
    if (t < SS * SS) { sW[0][t] = WA[t]; sW[1][t] = WB[t]; }
    if (t < 2 * SS)  { sa[0][t] = avA[t]; sa[1][t] = avB[t]; }
    __syncthreads();
    int idx = blockIdx.x * blockDim.x + t;
    if (idx >= 2 * NN) return;
    int set = idx >> 13;
    int n = idx & (NN - 1);
    const float* Xin = feat_ptr(set == 0 ? xcodeA : xcodeB);   // batch 0 slice
    float xr[SS];
    {
        const float4* p4 = reinterpret_cast<const float4*>(Xin + (size_t)n * SS);
#pragma unroll
        for (int q = 0; q < 3; q++) {
            float4 v = p4[q];
            xr[q * 4 + 0] = v.x; xr[q * 4 + 1] = v.y;
            xr[q * 4 + 2] = v.z; xr[q * 4 + 3] = v.w;
        }
    }
    float ha = 0.f, hb = 0.f;
#pragma unroll
    for (int sp = 0; sp < SS; sp++) {
        float h = 0.f;
#pragma unroll
        for (int s = 0; s < SS; s++) h += xr[s] * sW[set][s * SS + sp];
        ha += h * sa[set][sp];
        hb += h * sa[set][SS + sp];
    }
    g_ha[set][n] = ha;
    g_hb[set][n] = hb;
    g_colsum[set][n] = 0.f;
    if (n < BB * SS) g_extra[set][n] = 0.f;
}

// position-parallel over BOTH sets, fully coalesced multp/csri/csrj/wp streams:
// representatives get exp(mult*val); colsum built via 32KB-resident atomics.
// Also accumulates the empty-column (uniform 1/N softmax) correction into g_extra.
__global__ void k_edgevals2(int xcodeA, int xcodeB,
                            const float* __restrict__ lw1, const float* __restrict__ lb1,
                            const float* __restrict__ lw2, const float* __restrict__ lb2) {
    int idx = blockIdx.x * blockDim.x + threadIdx.x;
    if (idx >= 2 * EE) return;
    int set = (idx >= EE) ? 1 : 0;
    int p = idx - set * EE;
    float lw = set ? lw2[0] : lw1[0];
    float lb = set ? lb2[0] : lb1[0];
    int m = g_multp[set][p];
    if (m == 0) {
        g_wp[set][p] = 0.f;
    } else {
        int i = g_csri[set][p];
        int j = g_csrj[set][p];
        float e = g_ha[set][i] + g_hb[set][j];
        e = (e > 0.f) ? e : 0.2f * e;                 // leaky_relu(0.2)
        float cell = (float)m * (e * lw + lb);
        float pe = __expf(cell);
        g_wp[set][p] = pe;
        atomicAdd(&g_colsum[set][j], pe);
    }
    if (p < NN && !g_colhas[set][p]) {                // column with no edges
        const float* X = feat_ptr(set == 0 ? xcodeA : xcodeB);
        for (int b = 0; b < BB; b++)
#pragma unroll
        for (int s = 0; s < SS; s++)
            atomicAdd(&g_extra[set][b * SS + s], X[((size_t)b * NN + p) * SS + s]);
    }
}

// fused SpMM gather + GCN over BOTH sets: thread = (set, i, b). Atomic-free.
// Inner loop streams wp/csrj contiguously; only X[j] row gather is indirect.
// z[b,i,:] = sum_{pos p in row i} (wp/colsum_j) * X[b, j, :]  (+ extra/N)
// C[b,i,:] = leaky_relu(z @ gcnW^T + gcnb, 0.01)
__global__ void k_gathergcn2(int xcodeA, int outA, int xcodeB, int outB,
                             const float* __restrict__ gcnW, const float* __restrict__ gcnb) {
    __shared__ float sW[SS * SS], sb[SS], sx[2][BB * SS];
    int t = threadIdx.x;
    if (t < SS * SS) sW[t] = gcnW[t];
    if (t < SS)      sb[t] = gcnb[t];
    if (t < BB * SS) { sx[0][t] = g_extra[0][t] * (1.0f / NN); sx[1][t] = g_extra[1][t] * (1.0f / NN); }
    __syncthreads();
    int idx = blockIdx.x * blockDim.x + t;
    if (idx >= 2 * BB * NN) return;
    int set = (idx >= BB * NN) ? 1 : 0;
    int r = idx - set * BB * NN;
    int i = r >> 2;                 // 4 adjacent lanes share row i (broadcast loads)
    int b = r & 3;
    const int* csrj = g_csrj[set];
    const float* wp = g_wp[set];
    const float* X = feat_ptr(set == 0 ? xcodeA : xcodeB) + (size_t)b * NN * SS;
    float acc[SS];
#pragma unroll
    for (int s = 0; s < SS; s++) acc[s] = sx[set][b * SS + s];
    int beg = g_rowptr[set][i], end = g_rowptr[set][i + 1];
#pragma unroll 4
    for (int p = beg; p < end; p++) {
        float w = wp[p];
        if (w != 0.f) {
            int j = csrj[p];
            float wn = __fdividef(w, g_colsum[set][j]);
            const float4* xr4 = reinterpret_cast<const float4*>(X + (size_t)j * SS);
#pragma unroll
            for (int q = 0; q < 3; q++) {
                float4 v = xr4[q];
                acc[q * 4 + 0] += wn * v.x; acc[q * 4 + 1] += wn * v.y;
                acc[q * 4 + 2] += wn * v.z; acc[q * 4 + 3] += wn * v.w;
            }
        }
    }
    float cout[SS];
#pragma unroll
    for (int sp = 0; sp < SS; sp++) {
        float v = sb[sp];
#pragma unroll
        for (int s = 0; s < SS; s++) v += acc[s] * sW[sp * SS + s];
        cout[sp] = (v > 0.f) ? v : 0.01f * v;
    }
    float4* C4 = reinterpret_cast<float4*>(feat_ptr(set == 0 ? outA : outB) + ((size_t)b * NN + i) * SS);
#pragma unroll
    for (int q = 0; q < 3; q++)
        C4[q] = make_float4(cout[q * 4], cout[q * 4 + 1], cout[q * 4 + 2], cout[q * 4 + 3]);
}

// ---------------- LSTM (2 layers, lockstep) + attention/FC tail ----------------

__device__ __forceinline__ void lstm_cell(const float* xt, float* h, float* c,
                                          const float* Wih, const float* Whh,
                                          const float* bias) {
    float zz[20];
#pragma unroll
    for (int u = 0; u < 20; u++) {
        float z = bias[u];
#pragma unroll
        for (int l = 0; l < 5; l++) z += xt[l] * Wih[u * 5 + l] + h[l] * Whh[u * 5 + l];
        zz[u] = z;
    }
#pragma unroll
    for (int u = 0; u < 5; u++) {
        float ig = sigf(zz[u]);
        float fg = sigf(zz[5 + u]);
        float gg = tanhfast(zz[10 + u]);
        float og = sigf(zz[15 + u]);
        c[u] = fg * c[u] + ig * gg;
        h[u] = og * tanhfast(c[u]);
    }
}

#define LSTM_TPB 128
#define FSTRIDE 61   // 60 floats used, padded to 61 (odd) -> conflict-free smem

__global__ void __launch_bounds__(LSTM_TPB)
k_lstm(const float* __restrict__ Wih0, const float* __restrict__ Whh0,
       const float* __restrict__ bih0, const float* __restrict__ bhh0,
       const float* __restrict__ Wih1, const float* __restrict__ Whh1,
       const float* __restrict__ bih1, const float* __restrict__ bhh1,
       const float* __restrict__ fc1W, const float* __restrict__ fc1b,
       const float* __restrict__ fc2W, const float* __restrict__ fc2b,
       const float* __restrict__ fc3W, const float* __restrict__ fc3b,
       float* __restrict__ out, int write_a) {
    __shared__ float sWih0[100], sWhh0[100], sb0[20];
    __shared__ float sWih1[100], sWhh1[100], sb1[20];
    __shared__ float sfc1W[KK * (SS - 1)], sfc1b[KK];
    __shared__ float sfc2W[LL * KK], sfc2b[LL];
    __shared__ float sfc3W[KK + LL], sfc3b0;
    __shared__ float sf[LSTM_TPB * FSTRIDE];
    int t = threadIdx.x;
    for (int u = t; u < 100; u += LSTM_TPB) {
        sWih0[u] = Wih0[u]; sWhh0[u] = Whh0[u];
        sWih1[u] = Wih1[u]; sWhh1[u] = Whh1[u];
    }
    if (t < 20)  { sb0[t] = bih0[t] + bhh0[t]; sb1[t] = bih1[t] + bhh1[t]; }
    for (int u = t; u < KK * (SS - 1); u += LSTM_TPB) sfc1W[u] = fc1W[u];
    if (t < KK)      sfc1b[t] = fc1b[t];
    if (t < LL * KK) sfc2W[t] = fc2W[t];
    if (t < LL)      sfc2b[t] = fc2b[t];
    if (t < KK + LL) sfc3W[t] = fc3W[t];
    if (t == 0)      sfc3b0 = fc3b[0];
    __syncthreads();

    int r = blockIdx.x * LSTM_TPB + t;   // row in [0, B*N)
    if (r >= BB * NN) return;
    size_t base = (size_t)r * SS;

    // coalesced float4 feature loads into padded shared (myf[l*SS+tt])
    float* myf = sf + t * FSTRIDE;
    {
        const float* srcs[5] = { g_xp + base, g_c1 + base, g_c2 + base, g_c4 + base, g_c5 + base };
#pragma unroll
        for (int l = 0; l < 5; l++) {
            const float4* p4 = reinterpret_cast<const float4*>(srcs[l]);
#pragma unroll
            for (int q = 0; q < 3; q++) {
                float4 v = p4[q];
                myf[l * SS + q * 4 + 0] = v.x; myf[l * SS + q * 4 + 1] = v.y;
                myf[l * SS + q * 4 + 2] = v.z; myf[l * SS + q * 4 + 3] = v.w;
            }
        }
    }

    float h0[5] = {0, 0, 0, 0, 0}, c0[5] = {0, 0, 0, 0, 0};
    float h1[5] = {0, 0, 0, 0, 0}, c1v[5] = {0, 0, 0, 0, 0};
    float Hc[5][KK];
#pragma unroll
    for (int l = 0; l < 5; l++)
#pragma unroll
        for (int k = 0; k < KK; k++) Hc[l][k] = sfc1b[k];

#pragma unroll
    for (int tt = 0; tt < SS; tt++) {
        float xt[5];
#pragma unroll
        for (int l = 0; l < 5; l++) xt[l] = myf[l * SS + tt];
        lstm_cell(xt, h0, c0, sWih0, sWhh0, sb0);
        lstm_cell(h0, h1, c1v, sWih1, sWhh1, sb1);
        if (tt < SS - 1) {
#pragma unroll
            for (int l = 0; l < 5; l++)
#pragma unroll
                for (int k = 0; k < KK; k++)
                    Hc[l][k] += h1[l] * sfc1W[k * (SS - 1) + tt];
        }
    }
    // h1 is now ht = lstm_out[:, -1, :]
    float a[5];
#pragma unroll
    for (int l = 0; l < 5; l++) {
        float acc = 0.f;
#pragma unroll
        for (int m = 0; m < 5; m++) {
            float hn = sfc2b[m];
#pragma unroll
            for (int k = 0; k < KK; k++) hn += Hc[l][k] * sfc2W[m * KK + k];
            acc += hn * h1[m];
        }
        a[l] = sigf(acc);
    }
    float y = sfc3b0;
#pragma unroll
    for (int k = 0; k < KK; k++) {
        float vt = 0.f;
#pragma unroll
        for (int l = 0; l < 5; l++) vt += a[l] * Hc[l][k];
        y += vt * sfc3W[k];
    }
#pragma unroll
    for (int l = 0; l < 5; l++) y += h1[l] * sfc3W[KK + l];

    out[r] = y;
    if (write_a) {
#pragma unroll
        for (int l = 0; l < 5; l++) out[BB * NN + (size_t)r * 5 + l] = a[l];
    }
}

// ---------------- host orchestration (launches only; graph-capture safe) --------

extern "C" void kernel_launch(void* const* d_in, const int* in_sizes, int n_in,
                              void* d_out, int out_size) {
    const float* x    = (const float*)d_in[0];
    const int*   e1   = (const int*)  d_in[1];
    const int*   e2   = (const int*)  d_in[2];
    const float* g1W  = (const float*)d_in[3];
    const float* g1a  = (const float*)d_in[4];
    const float* g1lw = (const float*)d_in[5];
    const float* g1lb = (const float*)d_in[6];
    const float* g2W  = (const float*)d_in[7];
    const float* g2a  = (const float*)d_in[8];
    const float* g2lw = (const float*)d_in[9];
    const float* g2lb = (const float*)d_in[10];
    const float* gcnW = (const float*)d_in[11];
    const float* gcnb = (const float*)d_in[12];
    const float* Wih0 = (const float*)d_in[13];
    const float* Whh0 = (const float*)d_in[14];
    const float* bih0 = (const float*)d_in[15];
    const float* bhh0 = (const float*)d_in[16];
    const float* Wih1 = (const float*)d_in[17];
    const float* Whh1 = (const float*)d_in[18];
    const float* bih1 = (const float*)d_in[19];
    const float* bhh1 = (const float*)d_in[20];
    const float* fc1W = (const float*)d_in[21];
    const float* fc1b = (const float*)d_in[22];
    const float* fc2W = (const float*)d_in[23];
    const float* fc2b = (const float*)d_in[24];
    const float* fc3W = (const float*)d_in[25];
    const float* fc3b = (const float*)d_in[26];
    float* out = (float*)d_out;

    // setup chain
    k_setup<<<(BB * SS * NN + 255) / 256, 256>>>(x, e1, e2);
    k_scan<<<1, 1024>>>();
    k_scatter<<<(2 * EE + 255) / 256, 256>>>(e1, e2);
    k_dedup<<<(2 * NN + 255) / 256, 256>>>();

    // super-round A: xp -> c1 (set0, g1) ; xp -> c4 (set1, g2)
    k_prep2<<<(2 * NN + 255) / 256, 256>>>(0, g1W, g1a, 0, g2W, g2a);
    k_edgevals2<<<(2 * EE + 255) / 256, 256>>>(0, 0, g1lw, g1lb, g2lw, g2lb);
    k_gathergcn2<<<(2 * BB * NN + 255) / 256, 256>>>(0, 1, 0, 3, gcnW, gcnb);

    // super-round B: c1 -> c2 (set0, g1) ; c4 -> c5 (set1, g2)
    k_prep2<<<(2 * NN + 255) / 256, 256>>>(1, g1W, g1a, 3, g2W, g2a);
    k_edgevals2<<<(2 * EE + 255) / 256, 256>>>(1, 3, g1lw, g1lb, g2lw, g2lb);
    k_gathergcn2<<<(2 * BB * NN + 255) / 256, 256>>>(1, 2, 3, 4, gcnW, gcnb);

    int write_a = (out_size >= BB * NN * (1 + LL)) ? 1 : 0;
    k_lstm<<<(BB * NN + LSTM_TPB - 1) / LSTM_TPB, LSTM_TPB>>>(
        Wih0, Whh0, bih0, bhh0, Wih1, Whh1, bih1, bhh1,
        fc1W, fc1b, fc2W, fc2b, fc3W, fc3b, out, write_a);
}